// round 5
// baseline (speedup 1.0000x reference)
#include <cuda_runtime.h>
#include <math.h>

// Problem dims (compile-time constants)
constexpr int B_   = 8;
constexpr int NQ_  = 512;
constexpr int NKV_ = 1024;
constexpr int D_   = 1024;
constexpr int H_   = 16;
constexpr int HD_  = 64;
constexpr int FF_  = 4096;

// ---------------- static scratch (no allocation allowed) ----------------
__device__ float g_q_in [(size_t)B_*NQ_*D_];
__device__ float g_kv_in[(size_t)B_*NKV_*D_];
__device__ float g_q    [(size_t)B_*NQ_*D_];
__device__ float g_k    [(size_t)B_*NKV_*D_];
__device__ float g_v    [(size_t)B_*NKV_*D_];
__device__ float g_attn [(size_t)B_*H_*NQ_*NKV_];   // 256 MB
__device__ float g_ctx  [(size_t)B_*NQ_*D_];
__device__ float g_x    [(size_t)B_*NQ_*D_];
__device__ float g_h    [(size_t)B_*NQ_*D_];
__device__ float g_ff   [(size_t)B_*NQ_*FF_];       // 64 MB

// ---------------- LayerNorm: one block per row of D_=1024 ----------------
__global__ void layernorm_kernel(const float* __restrict__ x,
                                 const float* __restrict__ gamma,
                                 const float* __restrict__ beta,
                                 float* __restrict__ out)
{
    __shared__ float sv[D_];
    __shared__ float red[256];
    const int row = blockIdx.x;
    const int tid = threadIdx.x;
    const float* xr = x + (size_t)row * D_;

    float ls = 0.f;
    for (int i = tid; i < D_; i += 256) { float v = xr[i]; sv[i] = v; ls += v; }
    red[tid] = ls; __syncthreads();
    for (int s = 128; s > 0; s >>= 1) { if (tid < s) red[tid] += red[tid + s]; __syncthreads(); }
    const float mu = red[0] * (1.f / D_);
    __syncthreads();

    float lv = 0.f;
    for (int i = tid; i < D_; i += 256) { float d = sv[i] - mu; lv += d * d; }
    red[tid] = lv; __syncthreads();
    for (int s = 128; s > 0; s >>= 1) { if (tid < s) red[tid] += red[tid + s]; __syncthreads(); }
    const float inv = rsqrtf(red[0] * (1.f / D_) + 1e-5f);

    float* orow = out + (size_t)row * D_;
    for (int i = tid; i < D_; i += 256)
        orow[i] = (sv[i] - mu) * inv * gamma[i] + beta[i];
}

// ---------------- generic SGEMM: C = A * op(W) (+bias)(+epi) ----------------
// TRANS_B=1: W is [N,K] row-major (use W^T)   TRANS_B=0: W is [K,N]
// EPI: 0 = none, 1 = exact gelu, 2 = add residual res[row*ldc+col]
// batch via blockIdx.z decomposed as (zb, zh) with independent strides.
// Requirements: M % 128 == 0, K % 8 == 0. N guarded.
template<int TRANS_B, int EPI>
__global__ __launch_bounds__(256)
void gemm_kernel(const float* __restrict__ A, const float* __restrict__ W,
                 const float* __restrict__ bias, const float* __restrict__ res,
                 float* __restrict__ C,
                 int M, int N, int K, int lda, int ldb, int ldc,
                 int batchH,
                 long sAb, long sAh, long sWb, long sWh, long sCb, long sCh)
{
    const int z  = blockIdx.z;
    const int zb = z / batchH;
    const int zh = z - zb * batchH;
    A   += zb * sAb + zh * sAh;
    W   += zb * sWb + zh * sWh;
    C   += zb * sCb + zh * sCh;

    __shared__ float As[8][128];
    __shared__ float Bs[8][128];

    const int tid = threadIdx.x;
    const int tx  = tid & 15;     // 0..15 -> 8 cols each
    const int ty  = tid >> 4;     // 0..15 -> 8 rows each
    const int bm  = blockIdx.y * 128;
    const int bn  = blockIdx.x * 128;

    float acc[8][8];
#pragma unroll
    for (int i = 0; i < 8; i++)
#pragma unroll
        for (int j = 0; j < 8; j++) acc[i][j] = 0.f;

    for (int k0 = 0; k0 < K; k0 += 8) {
        // A tile: 128 x 8
#pragma unroll
        for (int i = 0; i < 4; i++) {
            int idx = tid + i * 256;
            int r = idx >> 3, c = idx & 7;
            As[c][r] = A[(size_t)(bm + r) * lda + (k0 + c)];
        }
        // B tile: 8 x 128 (Bs[k][n])
#pragma unroll
        for (int i = 0; i < 4; i++) {
            int idx = tid + i * 256;
            if (TRANS_B) {
                int n = idx >> 3, c = idx & 7;
                Bs[c][n] = (bn + n < N) ? W[(size_t)(bn + n) * ldb + (k0 + c)] : 0.f;
            } else {
                int r = idx >> 7, n = idx & 127;
                Bs[r][n] = (bn + n < N) ? W[(size_t)(k0 + r) * ldb + (bn + n)] : 0.f;
            }
        }
        __syncthreads();

#pragma unroll
        for (int kk = 0; kk < 8; kk++) {
            float a[8], b[8];
#pragma unroll
            for (int i = 0; i < 8; i++) a[i] = As[kk][ty * 8 + i];
#pragma unroll
            for (int j = 0; j < 8; j++) b[j] = Bs[kk][tx * 8 + j];
#pragma unroll
            for (int i = 0; i < 8; i++)
#pragma unroll
                for (int j = 0; j < 8; j++)
                    acc[i][j] = fmaf(a[i], b[j], acc[i][j]);
        }
        __syncthreads();
    }

#pragma unroll
    for (int i = 0; i < 8; i++) {
        const int row = bm + ty * 8 + i;
#pragma unroll
        for (int j = 0; j < 8; j++) {
            const int col = bn + tx * 8 + j;
            if (col < N) {
                float v = acc[i][j];
                if (bias) v += bias[col];
                if (EPI == 1) v = 0.5f * v * (1.0f + erff(v * 0.70710678118654752f));
                if (EPI == 2) v += res[(size_t)row * ldc + col];
                C[(size_t)row * ldc + col] = v;
            }
        }
    }
}

// ---------------- scale + mask + softmax over NKV_ (in place) ----------------
// mask is int32 (jax bool materialized as int32 by the harness)
__global__ void softmax_kernel(float* __restrict__ S, const int* __restrict__ mask)
{
    __shared__ float sv[NKV_];
    __shared__ float red[256];
    const int row = blockIdx.x;                    // B*H*NQ rows
    const int tid = threadIdx.x;
    const int b   = row / (H_ * NQ_);
    float* sr = S + (size_t)row * NKV_;
    const int* mr = mask + (size_t)b * NKV_;

    const float scale = 0.125f;                    // 1/sqrt(64)
    float lm = -3.4028235e38f;
    for (int i = tid; i < NKV_; i += 256) {
        float v = sr[i] * scale;
        if (mr[i] != 0) v = -3.4028235e38f;
        sv[i] = v;
        lm = fmaxf(lm, v);
    }
    red[tid] = lm; __syncthreads();
    for (int s = 128; s > 0; s >>= 1) { if (tid < s) red[tid] = fmaxf(red[tid], red[tid + s]); __syncthreads(); }
    const float m = red[0];
    __syncthreads();

    float lsum = 0.f;
    for (int i = tid; i < NKV_; i += 256) {
        float e = __expf(sv[i] - m);
        sv[i] = e;
        lsum += e;
    }
    red[tid] = lsum; __syncthreads();
    for (int s = 128; s > 0; s >>= 1) { if (tid < s) red[tid] += red[tid + s]; __syncthreads(); }
    const float inv = 1.f / red[0];
    for (int i = tid; i < NKV_; i += 256) sr[i] = sv[i] * inv;
}

// ---------------- attn_weights = mean over heads ----------------
__global__ void attn_mean_kernel(const float* __restrict__ attn, float* __restrict__ out)
{
    const size_t idx = (size_t)blockIdx.x * 256 + threadIdx.x;  // B*NQ*NKV
    const int k = (int)(idx & (NKV_ - 1));
    const size_t t = idx >> 10;                                 // / NKV_
    const int q = (int)(t & (NQ_ - 1));
    const int b = (int)(t >> 9);                                // / NQ_
    float s = 0.f;
#pragma unroll
    for (int h = 0; h < H_; h++)
        s += attn[(((size_t)(b * H_ + h) * NQ_) + q) * NKV_ + k];
    out[idx] = s * (1.f / H_);
}

// ---------------- launch ----------------
extern "C" void kernel_launch(void* const* d_in, const int* in_sizes, int n_in,
                              void* d_out, int out_size)
{
    const float* query     = (const float*)d_in[0];
    const float* key_value = (const float*)d_in[1];
    const int*   mask      = (const int*)d_in[2];
    const float* nq_g  = (const float*)d_in[3];
    const float* nq_b  = (const float*)d_in[4];
    const float* nkv_g = (const float*)d_in[5];
    const float* nkv_b = (const float*)d_in[6];
    const float* w_in  = (const float*)d_in[7];
    const float* b_in  = (const float*)d_in[8];
    const float* w_out = (const float*)d_in[9];
    const float* b_out = (const float*)d_in[10];
    const float* nff_g = (const float*)d_in[11];
    const float* nff_b = (const float*)d_in[12];
    const float* w_ff1 = (const float*)d_in[13];
    const float* b_ff1 = (const float*)d_in[14];
    const float* w_ff2 = (const float*)d_in[15];
    const float* b_ff2 = (const float*)d_in[16];

    float* out_x  = (float*)d_out;
    float* out_aw = out_x + (size_t)B_ * NQ_ * D_;

    float *q_in, *kv_in, *qb, *kb, *vb, *attn, *ctx, *xb, *hb, *ffb;
    cudaGetSymbolAddress((void**)&q_in,  g_q_in);
    cudaGetSymbolAddress((void**)&kv_in, g_kv_in);
    cudaGetSymbolAddress((void**)&qb,    g_q);
    cudaGetSymbolAddress((void**)&kb,    g_k);
    cudaGetSymbolAddress((void**)&vb,    g_v);
    cudaGetSymbolAddress((void**)&attn,  g_attn);
    cudaGetSymbolAddress((void**)&ctx,   g_ctx);
    cudaGetSymbolAddress((void**)&xb,    g_x);
    cudaGetSymbolAddress((void**)&hb,    g_h);
    cudaGetSymbolAddress((void**)&ffb,   g_ff);

    // 1) pre-layernorms
    layernorm_kernel<<<B_*NQ_, 256>>>(query, nq_g, nq_b, q_in);
    layernorm_kernel<<<B_*NKV_, 256>>>(key_value, nkv_g, nkv_b, kv_in);

    // 2) Q/K/V projections (C = A @ W^T + b)
    dim3 gq(D_/128, (B_*NQ_)/128, 1);
    gemm_kernel<1,0><<<gq, 256>>>(q_in, w_in, b_in, nullptr, qb,
        B_*NQ_, D_, D_, D_, D_, D_, 1, 0,0,0,0,0,0);
    dim3 gkv(D_/128, (B_*NKV_)/128, 1);
    gemm_kernel<1,0><<<gkv, 256>>>(kv_in, w_in + (size_t)D_*D_, b_in + D_, nullptr, kb,
        B_*NKV_, D_, D_, D_, D_, D_, 1, 0,0,0,0,0,0);
    gemm_kernel<1,0><<<gkv, 256>>>(kv_in, w_in + (size_t)2*D_*D_, b_in + 2*D_, nullptr, vb,
        B_*NKV_, D_, D_, D_, D_, D_, 1, 0,0,0,0,0,0);

    // 3) scores: per (b,h), S = Q_bh @ K_bh^T   [512 x 1024, K=64]
    dim3 gs(NKV_/128, NQ_/128, B_*H_);
    gemm_kernel<1,0><<<gs, 256>>>(qb, kb, nullptr, nullptr, attn,
        NQ_, NKV_, HD_, D_, D_, NKV_, H_,
        (long)NQ_*D_, (long)HD_, (long)NKV_*D_, (long)HD_,
        (long)H_*NQ_*NKV_, (long)NQ_*NKV_);

    // 4) scale + mask + softmax (in place) ; then head-mean to output
    softmax_kernel<<<B_*H_*NQ_, 256>>>(attn, mask);
    attn_mean_kernel<<<(B_*NQ_*NKV_)/256, 256>>>(attn, out_aw);

    // 5) ctx: per (b,h), C = attn_bh @ V_bh   [512 x 64, K=1024]
    dim3 gc(1, NQ_/128, B_*H_);
    gemm_kernel<0,0><<<gc, 256>>>(attn, vb, nullptr, nullptr, ctx,
        NQ_, HD_, NKV_, NKV_, D_, D_, H_,
        (long)H_*NQ_*NKV_, (long)NQ_*NKV_, (long)NKV_*D_, (long)HD_,
        (long)NQ_*D_, (long)HD_);

    // 6) out projection + residual: x = query + ctx @ Wo^T + bo
    gemm_kernel<1,2><<<gq, 256>>>(ctx, w_out, b_out, query, xb,
        B_*NQ_, D_, D_, D_, D_, D_, 1, 0,0,0,0,0,0);

    // 7) FFN
    layernorm_kernel<<<B_*NQ_, 256>>>(xb, nff_g, nff_b, hb);
    dim3 gf1(FF_/128, (B_*NQ_)/128, 1);
    gemm_kernel<1,1><<<gf1, 256>>>(hb, w_ff1, b_ff1, nullptr, ffb,
        B_*NQ_, FF_, D_, D_, D_, FF_, 1, 0,0,0,0,0,0);
    gemm_kernel<1,2><<<gq, 256>>>(ffb, w_ff2, b_ff2, xb, out_x,
        B_*NQ_, D_, FF_, FF_, FF_, D_, 1, 0,0,0,0,0,0);
}

// round 6
// speedup vs baseline: 1.5130x; 1.5130x over previous
#include <cuda_runtime.h>
#include <math.h>
#include <stdint.h>

// Problem dims (compile-time constants)
constexpr int B_   = 8;
constexpr int NQ_  = 512;
constexpr int NKV_ = 1024;
constexpr int D_   = 1024;
constexpr int H_   = 16;
constexpr int HD_  = 64;
constexpr int FF_  = 4096;

// ---------------- static scratch (no allocation allowed) ----------------
__device__ float g_q_in [(size_t)B_*NQ_*D_];
__device__ float g_kv_in[(size_t)B_*NKV_*D_];
__device__ float g_q    [(size_t)B_*NQ_*D_];
__device__ float g_k    [(size_t)B_*NKV_*D_];
__device__ float g_v    [(size_t)B_*NKV_*D_];
__device__ float g_attn [(size_t)B_*H_*NQ_*NKV_];   // 256 MB
__device__ float g_ctx  [(size_t)B_*NQ_*D_];
__device__ float g_x    [(size_t)B_*NQ_*D_];
__device__ float g_h    [(size_t)B_*NQ_*D_];
__device__ float g_ff   [(size_t)B_*NQ_*FF_];       // 64 MB

// ---------------- LayerNorm: one block per row of D_=1024 ----------------
__global__ void layernorm_kernel(const float* __restrict__ x,
                                 const float* __restrict__ gamma,
                                 const float* __restrict__ beta,
                                 float* __restrict__ out)
{
    __shared__ float sv[D_];
    __shared__ float red[256];
    const int row = blockIdx.x;
    const int tid = threadIdx.x;
    const float* xr = x + (size_t)row * D_;

    float ls = 0.f;
    for (int i = tid; i < D_; i += 256) { float v = xr[i]; sv[i] = v; ls += v; }
    red[tid] = ls; __syncthreads();
    for (int s = 128; s > 0; s >>= 1) { if (tid < s) red[tid] += red[tid + s]; __syncthreads(); }
    const float mu = red[0] * (1.f / D_);
    __syncthreads();

    float lv = 0.f;
    for (int i = tid; i < D_; i += 256) { float d = sv[i] - mu; lv += d * d; }
    red[tid] = lv; __syncthreads();
    for (int s = 128; s > 0; s >>= 1) { if (tid < s) red[tid] += red[tid + s]; __syncthreads(); }
    const float inv = rsqrtf(red[0] * (1.f / D_) + 1e-5f);

    float* orow = out + (size_t)row * D_;
    for (int i = tid; i < D_; i += 256)
        orow[i] = (sv[i] - mu) * inv * gamma[i] + beta[i];
}

// ---------------- TF32 helpers ----------------
__device__ __forceinline__ uint32_t f2tf(float x) {
    uint32_t r;
    asm("cvt.rna.tf32.f32 %0, %1;" : "=r"(r) : "f"(x));
    return r;
}

__device__ __forceinline__ void mma_tf32(float* c,
                                         uint32_t a0, uint32_t a1, uint32_t a2, uint32_t a3,
                                         uint32_t b0, uint32_t b1)
{
    asm("mma.sync.aligned.m16n8k8.row.col.f32.tf32.tf32.f32 "
        "{%0,%1,%2,%3}, {%4,%5,%6,%7}, {%8,%9}, {%0,%1,%2,%3};"
        : "+f"(c[0]), "+f"(c[1]), "+f"(c[2]), "+f"(c[3])
        : "r"(a0), "r"(a1), "r"(a2), "r"(a3), "r"(b0), "r"(b1));
}

// ---------------- TF32 (3x-split) GEMM: C = A * op(W) (+bias)(+epi) ----------------
// TRANS_B=1: W is [N,K] row-major (use W^T)   TRANS_B=0: W is [K,N]
// EPI: 0 = none, 1 = exact gelu, 2 = add residual res[row*ldc+col]
// Requirements: M % 128 == 0, K % 32 == 0, lda/ldb/ldc % 4 == 0, N % 4 == 0. N guarded vs 128-tile.
template<int TRANS_B, int EPI>
__global__ __launch_bounds__(256)
void gemm_tf32(const float* __restrict__ A, const float* __restrict__ W,
               const float* __restrict__ bias, const float* __restrict__ res,
               float* __restrict__ C,
               int M, int N, int K, int lda, int ldb, int ldc,
               int batchH,
               long sAb, long sAh, long sWb, long sWh, long sCb, long sCh)
{
    const int z  = blockIdx.z;
    const int zb = z / batchH;
    const int zh = z - zb * batchH;
    A += zb * sAb + zh * sAh;
    W += zb * sWb + zh * sWh;
    C += zb * sCb + zh * sCh;

    __shared__ __align__(16) float As[128][36];   // [m][k], pad 32->36
    __shared__ __align__(16) float Bs[128][36];   // [n][k], pad 32->36

    const int tid  = threadIdx.x;
    const int lane = tid & 31;
    const int warp = tid >> 5;
    const int wm   = warp & 1;        // 2 warps over M  (64 rows each)
    const int wn   = warp >> 1;       // 4 warps over N  (32 cols each)
    const int bm   = blockIdx.y * 128;
    const int bn   = blockIdx.x * 128;

    const int lq = lane >> 2;         // 0..7
    const int lr = lane & 3;          // 0..3

    float acc[4][4][4];
#pragma unroll
    for (int i = 0; i < 4; i++)
#pragma unroll
        for (int j = 0; j < 4; j++)
#pragma unroll
            for (int e = 0; e < 4; e++) acc[i][j][e] = 0.f;

    for (int k0 = 0; k0 < K; k0 += 32) {
        // ---- load A tile: 128 x 32 (float4) ----
#pragma unroll
        for (int i = 0; i < 4; i++) {
            int f4 = tid + i * 256;
            int r = f4 >> 3, c4 = f4 & 7;
            float4 v = *reinterpret_cast<const float4*>(&A[(size_t)(bm + r) * lda + k0 + c4 * 4]);
            *reinterpret_cast<float4*>(&As[r][c4 * 4]) = v;
        }
        // ---- load B tile into Bs[n][k] ----
        if (TRANS_B) {
#pragma unroll
            for (int i = 0; i < 4; i++) {
                int f4 = tid + i * 256;
                int r = f4 >> 3, c4 = f4 & 7;
                float4 v;
                if (bn + r < N)
                    v = *reinterpret_cast<const float4*>(&W[(size_t)(bn + r) * ldb + k0 + c4 * 4]);
                else
                    v = make_float4(0.f, 0.f, 0.f, 0.f);
                *reinterpret_cast<float4*>(&Bs[r][c4 * 4]) = v;
            }
        } else {
#pragma unroll
            for (int i = 0; i < 4; i++) {
                int f4 = tid + i * 256;
                int k = f4 >> 5, n4 = f4 & 31;
                float4 v;
                if (bn + n4 * 4 + 3 < N)
                    v = *reinterpret_cast<const float4*>(&W[(size_t)(k0 + k) * ldb + bn + n4 * 4]);
                else
                    v = make_float4(0.f, 0.f, 0.f, 0.f);
                Bs[n4 * 4 + 0][k] = v.x;
                Bs[n4 * 4 + 1][k] = v.y;
                Bs[n4 * 4 + 2][k] = v.z;
                Bs[n4 * 4 + 3][k] = v.w;
            }
        }
        __syncthreads();

#pragma unroll
        for (int kk = 0; kk < 32; kk += 8) {
            // B fragments for this k-step (hi/lo)
            uint32_t bh[4][2], bl[4][2];
#pragma unroll
            for (int nf = 0; nf < 4; nf++) {
                int n = wn * 32 + nf * 8 + lq;
                float x0 = Bs[n][kk + lr];
                float x1 = Bs[n][kk + lr + 4];
                bh[nf][0] = f2tf(x0);
                bl[nf][0] = f2tf(x0 - __uint_as_float(bh[nf][0]));
                bh[nf][1] = f2tf(x1);
                bl[nf][1] = f2tf(x1 - __uint_as_float(bh[nf][1]));
            }
#pragma unroll
            for (int mf = 0; mf < 4; mf++) {
                int m = wm * 64 + mf * 16 + lq;
                float a0 = As[m][kk + lr];
                float a1 = As[m + 8][kk + lr];
                float a2 = As[m][kk + lr + 4];
                float a3 = As[m + 8][kk + lr + 4];
                uint32_t ah0 = f2tf(a0), ah1 = f2tf(a1), ah2 = f2tf(a2), ah3 = f2tf(a3);
                uint32_t al0 = f2tf(a0 - __uint_as_float(ah0));
                uint32_t al1 = f2tf(a1 - __uint_as_float(ah1));
                uint32_t al2 = f2tf(a2 - __uint_as_float(ah2));
                uint32_t al3 = f2tf(a3 - __uint_as_float(ah3));
#pragma unroll
                for (int nf = 0; nf < 4; nf++) {
                    mma_tf32(acc[mf][nf], ah0, ah1, ah2, ah3, bh[nf][0], bh[nf][1]);
                    mma_tf32(acc[mf][nf], ah0, ah1, ah2, ah3, bl[nf][0], bl[nf][1]);
                    mma_tf32(acc[mf][nf], al0, al1, al2, al3, bh[nf][0], bh[nf][1]);
                }
            }
        }
        __syncthreads();
    }

    // ---- epilogue ----
#pragma unroll
    for (int mf = 0; mf < 4; mf++) {
        const int r0 = bm + wm * 64 + mf * 16 + lq;
#pragma unroll
        for (int nf = 0; nf < 4; nf++) {
            const int c0 = bn + wn * 32 + nf * 8 + lr * 2;
#pragma unroll
            for (int e = 0; e < 4; e++) {
                const int row = r0 + (e >> 1) * 8;
                const int col = c0 + (e & 1);
                if (col < N) {
                    float v = acc[mf][nf][e];
                    if (bias) v += bias[col];
                    if (EPI == 1) v = 0.5f * v * (1.0f + erff(v * 0.70710678118654752f));
                    if (EPI == 2) v += res[(size_t)row * ldc + col];
                    C[(size_t)row * ldc + col] = v;
                }
            }
        }
    }
}

// ---------------- scale + mask + softmax over NKV_ (in place) ----------------
// mask is int32 (jax bool materialized as int32 by the harness)
__global__ void softmax_kernel(float* __restrict__ S, const int* __restrict__ mask)
{
    __shared__ float sv[NKV_];
    __shared__ float red[256];
    const int row = blockIdx.x;                    // B*H*NQ rows
    const int tid = threadIdx.x;
    const int b   = row / (H_ * NQ_);
    float* sr = S + (size_t)row * NKV_;
    const int* mr = mask + (size_t)b * NKV_;

    const float scale = 0.125f;                    // 1/sqrt(64)
    float lm = -3.4028235e38f;
    for (int i = tid; i < NKV_; i += 256) {
        float v = sr[i] * scale;
        if (mr[i] != 0) v = -3.4028235e38f;
        sv[i] = v;
        lm = fmaxf(lm, v);
    }
    red[tid] = lm; __syncthreads();
    for (int s = 128; s > 0; s >>= 1) { if (tid < s) red[tid] = fmaxf(red[tid], red[tid + s]); __syncthreads(); }
    const float m = red[0];
    __syncthreads();

    float lsum = 0.f;
    for (int i = tid; i < NKV_; i += 256) {
        float e = __expf(sv[i] - m);
        sv[i] = e;
        lsum += e;
    }
    red[tid] = lsum; __syncthreads();
    for (int s = 128; s > 0; s >>= 1) { if (tid < s) red[tid] += red[tid + s]; __syncthreads(); }
    const float inv = 1.f / red[0];
    for (int i = tid; i < NKV_; i += 256) sr[i] = sv[i] * inv;
}

// ---------------- attn_weights = mean over heads ----------------
__global__ void attn_mean_kernel(const float* __restrict__ attn, float* __restrict__ out)
{
    const size_t idx = (size_t)blockIdx.x * 256 + threadIdx.x;  // B*NQ*NKV
    const int k = (int)(idx & (NKV_ - 1));
    const size_t t = idx >> 10;                                 // / NKV_
    const int q = (int)(t & (NQ_ - 1));
    const int b = (int)(t >> 9);                                // / NQ_
    float s = 0.f;
#pragma unroll
    for (int h = 0; h < H_; h++)
        s += attn[(((size_t)(b * H_ + h) * NQ_) + q) * NKV_ + k];
    out[idx] = s * (1.f / H_);
}

// ---------------- launch ----------------
extern "C" void kernel_launch(void* const* d_in, const int* in_sizes, int n_in,
                              void* d_out, int out_size)
{
    const float* query     = (const float*)d_in[0];
    const float* key_value = (const float*)d_in[1];
    const int*   mask      = (const int*)d_in[2];
    const float* nq_g  = (const float*)d_in[3];
    const float* nq_b  = (const float*)d_in[4];
    const float* nkv_g = (const float*)d_in[5];
    const float* nkv_b = (const float*)d_in[6];
    const float* w_in  = (const float*)d_in[7];
    const float* b_in  = (const float*)d_in[8];
    const float* w_out = (const float*)d_in[9];
    const float* b_out = (const float*)d_in[10];
    const float* nff_g = (const float*)d_in[11];
    const float* nff_b = (const float*)d_in[12];
    const float* w_ff1 = (const float*)d_in[13];
    const float* b_ff1 = (const float*)d_in[14];
    const float* w_ff2 = (const float*)d_in[15];
    const float* b_ff2 = (const float*)d_in[16];

    float* out_x  = (float*)d_out;
    float* out_aw = out_x + (size_t)B_ * NQ_ * D_;

    float *q_in, *kv_in, *qb, *kb, *vb, *attn, *ctx, *xb, *hb, *ffb;
    cudaGetSymbolAddress((void**)&q_in,  g_q_in);
    cudaGetSymbolAddress((void**)&kv_in, g_kv_in);
    cudaGetSymbolAddress((void**)&qb,    g_q);
    cudaGetSymbolAddress((void**)&kb,    g_k);
    cudaGetSymbolAddress((void**)&vb,    g_v);
    cudaGetSymbolAddress((void**)&attn,  g_attn);
    cudaGetSymbolAddress((void**)&ctx,   g_ctx);
    cudaGetSymbolAddress((void**)&xb,    g_x);
    cudaGetSymbolAddress((void**)&hb,    g_h);
    cudaGetSymbolAddress((void**)&ffb,   g_ff);

    // 1) pre-layernorms
    layernorm_kernel<<<B_*NQ_, 256>>>(query, nq_g, nq_b, q_in);
    layernorm_kernel<<<B_*NKV_, 256>>>(key_value, nkv_g, nkv_b, kv_in);

    // 2) Q/K/V projections (C = A @ W^T + b)
    dim3 gq(D_/128, (B_*NQ_)/128, 1);
    gemm_tf32<1,0><<<gq, 256>>>(q_in, w_in, b_in, nullptr, qb,
        B_*NQ_, D_, D_, D_, D_, D_, 1, 0,0,0,0,0,0);
    dim3 gkv(D_/128, (B_*NKV_)/128, 1);
    gemm_tf32<1,0><<<gkv, 256>>>(kv_in, w_in + (size_t)D_*D_, b_in + D_, nullptr, kb,
        B_*NKV_, D_, D_, D_, D_, D_, 1, 0,0,0,0,0,0);
    gemm_tf32<1,0><<<gkv, 256>>>(kv_in, w_in + (size_t)2*D_*D_, b_in + 2*D_, nullptr, vb,
        B_*NKV_, D_, D_, D_, D_, D_, 1, 0,0,0,0,0,0);

    // 3) scores: per (b,h), S = Q_bh @ K_bh^T   [512 x 1024, K=64]
    dim3 gs(NKV_/128, NQ_/128, B_*H_);
    gemm_tf32<1,0><<<gs, 256>>>(qb, kb, nullptr, nullptr, attn,
        NQ_, NKV_, HD_, D_, D_, NKV_, H_,
        (long)NQ_*D_, (long)HD_, (long)NKV_*D_, (long)HD_,
        (long)H_*NQ_*NKV_, (long)NQ_*NKV_);

    // 4) scale + mask + softmax (in place) ; then head-mean to output
    softmax_kernel<<<B_*H_*NQ_, 256>>>(attn, mask);
    attn_mean_kernel<<<(B_*NQ_*NKV_)/256, 256>>>(attn, out_aw);

    // 5) ctx: per (b,h), C = attn_bh @ V_bh   [512 x 64, K=1024]
    dim3 gc(1, NQ_/128, B_*H_);
    gemm_tf32<0,0><<<gc, 256>>>(attn, vb, nullptr, nullptr, ctx,
        NQ_, HD_, NKV_, NKV_, D_, D_, H_,
        (long)H_*NQ_*NKV_, (long)NQ_*NKV_, (long)NKV_*D_, (long)HD_,
        (long)NQ_*D_, (long)HD_);

    // 6) out projection + residual: x = query + ctx @ Wo^T + bo
    gemm_tf32<1,2><<<gq, 256>>>(ctx, w_out, b_out, query, xb,
        B_*NQ_, D_, D_, D_, D_, D_, 1, 0,0,0,0,0,0);

    // 7) FFN
    layernorm_kernel<<<B_*NQ_, 256>>>(xb, nff_g, nff_b, hb);
    dim3 gf1(FF_/128, (B_*NQ_)/128, 1);
    gemm_tf32<1,1><<<gf1, 256>>>(hb, w_ff1, b_ff1, nullptr, ffb,
        B_*NQ_, FF_, D_, D_, D_, FF_, 1, 0,0,0,0,0,0);
    gemm_tf32<1,2><<<gq, 256>>>(ffb, w_ff2, b_ff2, xb, out_x,
        B_*NQ_, D_, FF_, FF_, FF_, D_, 1, 0,0,0,0,0,0);
}

// round 8
// speedup vs baseline: 2.4289x; 1.6054x over previous
#include <cuda_runtime.h>
#include <math.h>
#include <stdint.h>

// Problem dims (compile-time constants)
constexpr int B_   = 8;
constexpr int NQ_  = 512;
constexpr int NKV_ = 1024;
constexpr int D_   = 1024;
constexpr int H_   = 16;
constexpr int HD_  = 64;
constexpr int FF_  = 4096;

// ---------------- static scratch (no allocation allowed) ----------------
__device__ float g_q_in [(size_t)B_*NQ_*D_];
__device__ float g_kv_in[(size_t)B_*NKV_*D_];
__device__ float g_q    [(size_t)B_*NQ_*D_];
__device__ float g_k    [(size_t)B_*NKV_*D_];
__device__ float g_v    [(size_t)B_*NKV_*D_];
__device__ float g_attn [(size_t)B_*H_*NQ_*NKV_];   // 256 MB
__device__ float g_ctx  [(size_t)B_*NQ_*D_];
__device__ float g_x    [(size_t)B_*NQ_*D_];
__device__ float g_h    [(size_t)B_*NQ_*D_];
__device__ float g_ff   [(size_t)B_*NQ_*FF_];       // 64 MB

// ---------------- LayerNorm: one block per row of D_=1024 ----------------
__global__ void layernorm_kernel(const float* __restrict__ x,
                                 const float* __restrict__ gamma,
                                 const float* __restrict__ beta,
                                 float* __restrict__ out)
{
    __shared__ float sv[D_];
    __shared__ float red[256];
    const int row = blockIdx.x;
    const int tid = threadIdx.x;
    const float* xr = x + (size_t)row * D_;

    float ls = 0.f;
    for (int i = tid; i < D_; i += 256) { float v = xr[i]; sv[i] = v; ls += v; }
    red[tid] = ls; __syncthreads();
    for (int s = 128; s > 0; s >>= 1) { if (tid < s) red[tid] += red[tid + s]; __syncthreads(); }
    const float mu = red[0] * (1.f / D_);
    __syncthreads();

    float lv = 0.f;
    for (int i = tid; i < D_; i += 256) { float d = sv[i] - mu; lv += d * d; }
    red[tid] = lv; __syncthreads();
    for (int s = 128; s > 0; s >>= 1) { if (tid < s) red[tid] += red[tid + s]; __syncthreads(); }
    const float inv = rsqrtf(red[0] * (1.f / D_) + 1e-5f);

    float* orow = out + (size_t)row * D_;
    for (int i = tid; i < D_; i += 256)
        orow[i] = (sv[i] - mu) * inv * gamma[i] + beta[i];
}

// ---------------- bf16 split helpers ----------------
// pack two floats (lo_k, hi_k) into bf16x2 word: lower half = first k element
__device__ __forceinline__ uint32_t pack_bf16x2(float x0, float x1) {
    uint32_t r;
    asm("cvt.rn.bf16x2.f32 %0, %1, %2;" : "=r"(r) : "f"(x1), "f"(x0));
    return r;
}
// unpack halves of a packed bf16x2 word back to float (exact)
__device__ __forceinline__ float bf16lo_f(uint32_t w) { return __uint_as_float(w << 16); }
__device__ __forceinline__ float bf16hi_f(uint32_t w) { return __uint_as_float(w & 0xffff0000u); }

// split pair (x0,x1) -> hi word + lo word (x = hi + lo exactly at ~16-17 bits)
__device__ __forceinline__ void split2(float x0, float x1, uint32_t& h, uint32_t& l) {
    h = pack_bf16x2(x0, x1);
    l = pack_bf16x2(x0 - bf16lo_f(h), x1 - bf16hi_f(h));
}

__device__ __forceinline__ void mma_bf16(float* c, const uint32_t* a, uint32_t b0, uint32_t b1)
{
    asm("mma.sync.aligned.m16n8k16.row.col.f32.bf16.bf16.f32 "
        "{%0,%1,%2,%3}, {%4,%5,%6,%7}, {%8,%9}, {%0,%1,%2,%3};"
        : "+f"(c[0]), "+f"(c[1]), "+f"(c[2]), "+f"(c[3])
        : "r"(a[0]), "r"(a[1]), "r"(a[2]), "r"(a[3]), "r"(b0), "r"(b1));
}

// ---------------- bf16 (2-way split, 4-term) GEMM: C = A * op(W) (+bias)(+epi) ----------
// TRANS_B=1: W is [N,K] row-major (use W^T)   TRANS_B=0: W is [K,N]
// EPI: 0 = none, 1 = exact gelu, 2 = add residual res[row*ldc+col]
// Requirements: M % 128 == 0, K % 32 == 0, lda/ldb % 4 == 0, N % 4 == 0. N guarded vs 128-tile.
template<int TRANS_B, int EPI>
__global__ __launch_bounds__(256, 2)
void gemm_bf16s(const float* __restrict__ A, const float* __restrict__ W,
                const float* __restrict__ bias, const float* __restrict__ res,
                float* __restrict__ C,
                int M, int N, int K, int lda, int ldb, int ldc,
                int batchH,
                long sAb, long sAh, long sWb, long sWh, long sCb, long sCh)
{
    const int z  = blockIdx.z;
    const int zb = z / batchH;
    const int zh = z - zb * batchH;
    A += zb * sAb + zh * sAh;
    W += zb * sWb + zh * sWh;
    C += zb * sCb + zh * sCh;

    // packed bf16x2 tiles, k2 = k/2 in [0,16), row stride 20 words -> conflict-free frags
    __shared__ __align__(16) uint32_t Ah[128][20];
    __shared__ __align__(16) uint32_t Al[128][20];
    __shared__ __align__(16) uint32_t Bh[128][20];
    __shared__ __align__(16) uint32_t Bl[128][20];

    const int tid  = threadIdx.x;
    const int lane = tid & 31;
    const int warp = tid >> 5;
    const int wm   = warp & 1;        // 2 warps over M  (64 rows each)
    const int wn   = warp >> 1;       // 4 warps over N  (32 cols each)
    const int bm   = blockIdx.y * 128;
    const int bn   = blockIdx.x * 128;

    const int lq = lane >> 2;         // group 0..7
    const int lr = lane & 3;          // 0..3

    float acc[4][4][4];
#pragma unroll
    for (int i = 0; i < 4; i++)
#pragma unroll
        for (int j = 0; j < 4; j++)
#pragma unroll
            for (int e = 0; e < 4; e++) acc[i][j][e] = 0.f;

    for (int k0 = 0; k0 < K; k0 += 32) {
        // ---- A tile: 128 rows x 32 k (float4 per thread x4) ----
#pragma unroll
        for (int i = 0; i < 4; i++) {
            int f4 = tid + i * 256;
            int r = f4 >> 3, c4 = f4 & 7;
            float4 v = *reinterpret_cast<const float4*>(&A[(size_t)(bm + r) * lda + k0 + c4 * 4]);
            uint32_t h0, l0, h1, l1;
            split2(v.x, v.y, h0, l0);
            split2(v.z, v.w, h1, l1);
            Ah[r][c4 * 2]     = h0;  Al[r][c4 * 2]     = l0;
            Ah[r][c4 * 2 + 1] = h1;  Al[r][c4 * 2 + 1] = l1;
        }
        // ---- B tile into B*[n][k2] ----
        if (TRANS_B) {
#pragma unroll
            for (int i = 0; i < 4; i++) {
                int f4 = tid + i * 256;
                int r = f4 >> 3, c4 = f4 & 7;
                float4 v;
                if (bn + r < N)
                    v = *reinterpret_cast<const float4*>(&W[(size_t)(bn + r) * ldb + k0 + c4 * 4]);
                else
                    v = make_float4(0.f, 0.f, 0.f, 0.f);
                uint32_t h0, l0, h1, l1;
                split2(v.x, v.y, h0, l0);
                split2(v.z, v.w, h1, l1);
                Bh[r][c4 * 2]     = h0;  Bl[r][c4 * 2]     = l0;
                Bh[r][c4 * 2 + 1] = h1;  Bl[r][c4 * 2 + 1] = l1;
            }
        } else {
            // W is [K,N]; each item handles (k2, n4): rows 2k2,2k2+1, cols n4*4..+3
#pragma unroll
            for (int i = 0; i < 2; i++) {
                int item = tid + i * 256;
                int k2 = item >> 5, n4 = item & 31;
                float4 x, y;
                if (bn + n4 * 4 + 3 < N) {
                    x = *reinterpret_cast<const float4*>(&W[(size_t)(k0 + 2 * k2)     * ldb + bn + n4 * 4]);
                    y = *reinterpret_cast<const float4*>(&W[(size_t)(k0 + 2 * k2 + 1) * ldb + bn + n4 * 4]);
                } else {
                    x = make_float4(0.f, 0.f, 0.f, 0.f);
                    y = make_float4(0.f, 0.f, 0.f, 0.f);
                }
                const float xs[4] = {x.x, x.y, x.z, x.w};
                const float ys[4] = {y.x, y.y, y.z, y.w};
#pragma unroll
                for (int j = 0; j < 4; j++) {
                    uint32_t h, l;
                    split2(xs[j], ys[j], h, l);
                    Bh[n4 * 4 + j][k2] = h;
                    Bl[n4 * 4 + j][k2] = l;
                }
            }
        }
        __syncthreads();

#pragma unroll
        for (int ks = 0; ks < 16; ks += 8) {   // two K=16 steps per tile
            uint32_t bh[4][2], bl[4][2];
#pragma unroll
            for (int nf = 0; nf < 4; nf++) {
                int n = wn * 32 + nf * 8 + lq;
                bh[nf][0] = Bh[n][ks + lr];
                bh[nf][1] = Bh[n][ks + lr + 4];
                bl[nf][0] = Bl[n][ks + lr];
                bl[nf][1] = Bl[n][ks + lr + 4];
            }
#pragma unroll
            for (int mf = 0; mf < 4; mf++) {
                int m = wm * 64 + mf * 16 + lq;
                uint32_t ah[4], al[4];
                ah[0] = Ah[m][ks + lr];      ah[1] = Ah[m + 8][ks + lr];
                ah[2] = Ah[m][ks + lr + 4];  ah[3] = Ah[m + 8][ks + lr + 4];
                al[0] = Al[m][ks + lr];      al[1] = Al[m + 8][ks + lr];
                al[2] = Al[m][ks + lr + 4];  al[3] = Al[m + 8][ks + lr + 4];
#pragma unroll
                for (int nf = 0; nf < 4; nf++) {
                    mma_bf16(acc[mf][nf], ah, bh[nf][0], bh[nf][1]);
                    mma_bf16(acc[mf][nf], ah, bl[nf][0], bl[nf][1]);
                    mma_bf16(acc[mf][nf], al, bh[nf][0], bh[nf][1]);
                    mma_bf16(acc[mf][nf], al, bl[nf][0], bl[nf][1]);
                }
            }
        }
        __syncthreads();
    }

    // ---- epilogue ----
#pragma unroll
    for (int mf = 0; mf < 4; mf++) {
        const int r0 = bm + wm * 64 + mf * 16 + lq;
#pragma unroll
        for (int nf = 0; nf < 4; nf++) {
            const int c0 = bn + wn * 32 + nf * 8 + lr * 2;
#pragma unroll
            for (int e = 0; e < 4; e++) {
                const int row = r0 + (e >> 1) * 8;
                const int col = c0 + (e & 1);
                if (col < N) {
                    float v = acc[mf][nf][e];
                    if (bias) v += bias[col];
                    if (EPI == 1) v = 0.5f * v * (1.0f + erff(v * 0.70710678118654752f));
                    if (EPI == 2) v += res[(size_t)row * ldc + col];
                    C[(size_t)row * ldc + col] = v;
                }
            }
        }
    }
}

// ---------------- scale + mask + softmax over NKV_ (in place) ----------------
// mask is int32 (jax bool materialized as int32 by the harness)
__global__ void softmax_kernel(float* __restrict__ S, const int* __restrict__ mask)
{
    __shared__ float sv[NKV_];
    __shared__ float red[256];
    const int row = blockIdx.x;                    // B*H*NQ rows
    const int tid = threadIdx.x;
    const int b   = row / (H_ * NQ_);
    float* sr = S + (size_t)row * NKV_;
    const int* mr = mask + (size_t)b * NKV_;

    const float scale = 0.125f;                    // 1/sqrt(64)
    float lm = -3.4028235e38f;
    for (int i = tid; i < NKV_; i += 256) {
        float v = sr[i] * scale;
        if (mr[i] != 0) v = -3.4028235e38f;
        sv[i] = v;
        lm = fmaxf(lm, v);
    }
    red[tid] = lm; __syncthreads();
    for (int s = 128; s > 0; s >>= 1) { if (tid < s) red[tid] = fmaxf(red[tid], red[tid + s]); __syncthreads(); }
    const float m = red[0];
    __syncthreads();

    float lsum = 0.f;
    for (int i = tid; i < NKV_; i += 256) {
        float e = __expf(sv[i] - m);
        sv[i] = e;
        lsum += e;
    }
    red[tid] = lsum; __syncthreads();
    for (int s = 128; s > 0; s >>= 1) { if (tid < s) red[tid] += red[tid + s]; __syncthreads(); }
    const float inv = 1.f / red[0];
    for (int i = tid; i < NKV_; i += 256) sr[i] = sv[i] * inv;
}

// ---------------- attn_weights = mean over heads ----------------
__global__ void attn_mean_kernel(const float* __restrict__ attn, float* __restrict__ out)
{
    const size_t idx = (size_t)blockIdx.x * 256 + threadIdx.x;  // B*NQ*NKV
    const int k = (int)(idx & (NKV_ - 1));
    const size_t t = idx >> 10;                                 // / NKV_
    const int q = (int)(t & (NQ_ - 1));
    const int b = (int)(t >> 9);                                // / NQ_
    float s = 0.f;
#pragma unroll
    for (int h = 0; h < H_; h++)
        s += attn[(((size_t)(b * H_ + h) * NQ_) + q) * NKV_ + k];
    out[idx] = s * (1.f / H_);
}

// ---------------- launch ----------------
extern "C" void kernel_launch(void* const* d_in, const int* in_sizes, int n_in,
                              void* d_out, int out_size)
{
    const float* query     = (const float*)d_in[0];
    const float* key_value = (const float*)d_in[1];
    const int*   mask      = (const int*)d_in[2];
    const float* nq_g  = (const float*)d_in[3];
    const float* nq_b  = (const float*)d_in[4];
    const float* nkv_g = (const float*)d_in[5];
    const float* nkv_b = (const float*)d_in[6];
    const float* w_in  = (const float*)d_in[7];
    const float* b_in  = (const float*)d_in[8];
    const float* w_out = (const float*)d_in[9];
    const float* b_out = (const float*)d_in[10];
    const float* nff_g = (const float*)d_in[11];
    const float* nff_b = (const float*)d_in[12];
    const float* w_ff1 = (const float*)d_in[13];
    const float* b_ff1 = (const float*)d_in[14];
    const float* w_ff2 = (const float*)d_in[15];
    const float* b_ff2 = (const float*)d_in[16];

    float* out_x  = (float*)d_out;
    float* out_aw = out_x + (size_t)B_ * NQ_ * D_;

    float *q_in, *kv_in, *qb, *kb, *vb, *attn, *ctx, *xb, *hb, *ffb;
    cudaGetSymbolAddress((void**)&q_in,  g_q_in);
    cudaGetSymbolAddress((void**)&kv_in, g_kv_in);
    cudaGetSymbolAddress((void**)&qb,    g_q);
    cudaGetSymbolAddress((void**)&kb,    g_k);
    cudaGetSymbolAddress((void**)&vb,    g_v);
    cudaGetSymbolAddress((void**)&attn,  g_attn);
    cudaGetSymbolAddress((void**)&ctx,   g_ctx);
    cudaGetSymbolAddress((void**)&xb,    g_x);
    cudaGetSymbolAddress((void**)&hb,    g_h);
    cudaGetSymbolAddress((void**)&ffb,   g_ff);

    // 1) pre-layernorms
    layernorm_kernel<<<B_*NQ_, 256>>>(query, nq_g, nq_b, q_in);
    layernorm_kernel<<<B_*NKV_, 256>>>(key_value, nkv_g, nkv_b, kv_in);

    // 2) Q/K/V projections (C = A @ W^T + b)
    dim3 gq(D_/128, (B_*NQ_)/128, 1);
    gemm_bf16s<1,0><<<gq, 256>>>(q_in, w_in, b_in, nullptr, qb,
        B_*NQ_, D_, D_, D_, D_, D_, 1, 0,0,0,0,0,0);
    dim3 gkv(D_/128, (B_*NKV_)/128, 1);
    gemm_bf16s<1,0><<<gkv, 256>>>(kv_in, w_in + (size_t)D_*D_, b_in + D_, nullptr, kb,
        B_*NKV_, D_, D_, D_, D_, D_, 1, 0,0,0,0,0,0);
    gemm_bf16s<1,0><<<gkv, 256>>>(kv_in, w_in + (size_t)2*D_*D_, b_in + 2*D_, nullptr, vb,
        B_*NKV_, D_, D_, D_, D_, D_, 1, 0,0,0,0,0,0);

    // 3) scores: per (b,h), S = Q_bh @ K_bh^T   [512 x 1024, K=64]
    dim3 gs(NKV_/128, NQ_/128, B_*H_);
    gemm_bf16s<1,0><<<gs, 256>>>(qb, kb, nullptr, nullptr, attn,
        NQ_, NKV_, HD_, D_, D_, NKV_, H_,
        (long)NQ_*D_, (long)HD_, (long)NKV_*D_, (long)HD_,
        (long)H_*NQ_*NKV_, (long)NQ_*NKV_);

    // 4) scale + mask + softmax (in place) ; then head-mean to output
    softmax_kernel<<<B_*H_*NQ_, 256>>>(attn, mask);
    attn_mean_kernel<<<(B_*NQ_*NKV_)/256, 256>>>(attn, out_aw);

    // 5) ctx: per (b,h), C = attn_bh @ V_bh   [512 x 64, K=1024]
    dim3 gc(1, NQ_/128, B_*H_);
    gemm_bf16s<0,0><<<gc, 256>>>(attn, vb, nullptr, nullptr, ctx,
        NQ_, HD_, NKV_, NKV_, D_, D_, H_,
        (long)H_*NQ_*NKV_, (long)NQ_*NKV_, (long)NKV_*D_, (long)HD_,
        (long)NQ_*D_, (long)HD_);

    // 6) out projection + residual: x = query + ctx @ Wo^T + bo
    gemm_bf16s<1,2><<<gq, 256>>>(ctx, w_out, b_out, query, xb,
        B_*NQ_, D_, D_, D_, D_, D_, 1, 0,0,0,0,0,0);

    // 7) FFN
    layernorm_kernel<<<B_*NQ_, 256>>>(xb, nff_g, nff_b, hb);
    dim3 gf1(FF_/128, (B_*NQ_)/128, 1);
    gemm_bf16s<1,1><<<gf1, 256>>>(hb, w_ff1, b_ff1, nullptr, ffb,
        B_*NQ_, FF_, D_, D_, D_, FF_, 1, 0,0,0,0,0,0);
    gemm_bf16s<1,2><<<gq, 256>>>(ffb, w_ff2, b_ff2, xb, out_x,
        B_*NQ_, D_, FF_, FF_, FF_, D_, 1, 0,0,0,0,0,0);
}